// round 7
// baseline (speedup 1.0000x reference)
#include <cuda_runtime.h>

// stepSSM fused kernel, R6: constants off the l1tex pipe.
//  - warp-uniform weights (fc1_w/b, fc_w/b, D) in __constant__ memory
//    (filled via cudaMemcpyToSymbolAsync D2D -> graph memcpy nodes);
//    compile-time indices -> LDCU on the uniform const port (no l1tex).
//  - q-dependent A/Bm/C in shared as float2 -> 6 LDS.64/layer (was 12 LDS.32).
//  - 4 threads/row, fully coalesced float4 streaming state I/O (R3 mapping).
//
// Inputs (metadata order):
//   0: x[B,4]  1: states[4,B,2,4,2]  2: fc1_w[2,4]  3: fc1_b[2]
//   4: fc_w[5,2,2]  5: fc_b[5,2]  6: A[4,2,4,2]  7: Bm[4,2,4,2]
//   8: C[4,1,2,4,2]  9: D[4,1,2]
// Output: h[B,2] ++ new_states[4,B,2,4,2]  (f32)

#define THREADS 256

// __constant__ layout (floats)
#define CC_FC1W 0    // 8
#define CC_FC1B 8    // 2
#define CC_FCW  10   // 20
#define CC_FCB  30   // 10
#define CC_D    40   // 8
#define CC_N    48

__constant__ float cst[CC_N];

__global__ __launch_bounds__(THREADS) void step_ssm_kernel(
    const float4* __restrict__ x,        // [B]
    const float4* __restrict__ states,   // [4*B*4] float4
    const float*  __restrict__ A,
    const float*  __restrict__ Bm,
    const float*  __restrict__ C,
    float2*       __restrict__ out_h,      // [B]
    float4*       __restrict__ out_states, // [4*B*4] float4
    int B)
{
    // sABC: [0..31]=A, [32..63]=Bm, [64..95]=C as float2 pairs.
    // pair v of array X corresponds to X[2v], X[2v+1]; inner index for
    // (layer i, quad q, pair j) is v = i*8 + q*2 + j.
    __shared__ float2 sABC[96];
    {
        int t = threadIdx.x;
        if (t < 96) {
            const float* src = (t < 32) ? A : (t < 64) ? Bm : C;
            int v = t & 31;
            sABC[t] = make_float2(src[2 * v], src[2 * v + 1]);
        }
    }
    __syncthreads();

    const int t   = blockIdx.x * blockDim.x + threadIdx.x;
    const int row = t >> 2;
    const int q   = t & 3;
    if (row >= B) return;

    const size_t layer_str = (size_t)B * 4;   // float4 units
    const size_t my_off    = (size_t)row * 4 + q;

    // front-load all global reads
    float4 st[4];
#pragma unroll
    for (int i = 0; i < 4; i++)
        st[i] = __ldcs(states + (size_t)i * layer_str + my_off);
    float4 xv = __ldg(x + row);

    // fc1 (uniform consts -> LDCU)
    float h0 = fmaf(xv.x, cst[CC_FC1W + 0], fmaf(xv.y, cst[CC_FC1W + 1],
               fmaf(xv.z, cst[CC_FC1W + 2], fmaf(xv.w, cst[CC_FC1W + 3], cst[CC_FC1B + 0]))));
    float h1 = fmaf(xv.x, cst[CC_FC1W + 4], fmaf(xv.y, cst[CC_FC1W + 5],
               fmaf(xv.z, cst[CC_FC1W + 6], fmaf(xv.w, cst[CC_FC1W + 7], cst[CC_FC1B + 1]))));

    const int hd = q >> 1;
    const int vq = q * 2;

#pragma unroll
    for (int i = 0; i < 4; i++) {
        const int v = i * 8 + vq;
        float2 a0 = sABC[v],      a1 = sABC[v + 1];
        float2 b0 = sABC[32 + v], b1 = sABC[32 + v + 1];
        float2 c0 = sABC[64 + v], c1 = sABC[64 + v + 1];

        const float u = (hd == 0) ? h0 : h1;

        float nr0 = fmaf(a0.x, st[i].x, fmaf(-a0.y, st[i].y, b0.x * u));
        float ni0 = fmaf(a0.x, st[i].y, fmaf( a0.y, st[i].x, b0.y * u));
        float nr1 = fmaf(a1.x, st[i].z, fmaf(-a1.y, st[i].w, b1.x * u));
        float ni1 = fmaf(a1.x, st[i].w, fmaf( a1.y, st[i].z, b1.y * u));

        __stcs(out_states + (size_t)i * layer_str + my_off,
               make_float4(nr0, ni0, nr1, ni1));

        // partial C-projection (2 f's), reduce over head pair, swap heads
        float acc = fmaf(c0.x, nr0, fmaf(-c0.y, ni0,
                    fmaf(c1.x, nr1, -c1.y * ni1)));
        acc += __shfl_xor_sync(0xFFFFFFFFu, acc, 1);

        float y = fmaf(2.0f, acc, u * cst[CC_D + i * 2 + hd]);
        y = (y >= 0.0f) ? y : 0.125f * y;
        float yo = __shfl_xor_sync(0xFFFFFFFFu, y, 2);
        float y0 = (hd == 0) ? y  : yo;
        float y1 = (hd == 0) ? yo : y;

        const int wb = CC_FCW + i * 4;
        h0 = fmaf(y0, cst[wb + 0], fmaf(y1, cst[wb + 1], cst[CC_FCB + i * 2 + 0]));
        h1 = fmaf(y0, cst[wb + 2], fmaf(y1, cst[wb + 3], cst[CC_FCB + i * 2 + 1]));
    }

    // fc10 — lane q==0 writes the contiguous float2
    if (q == 0) {
        const int wb = CC_FCW + 16;
        float o0 = fmaf(h0, cst[wb + 0], fmaf(h1, cst[wb + 1], cst[CC_FCB + 8]));
        float o1 = fmaf(h0, cst[wb + 2], fmaf(h1, cst[wb + 3], cst[CC_FCB + 9]));
        out_h[row] = make_float2(o0, o1);
    }
}

extern "C" void kernel_launch(void* const* d_in, const int* in_sizes, int n_in,
                              void* d_out, int out_size)
{
    const float* x     = (const float*)d_in[0];
    const float* states= (const float*)d_in[1];
    const float* fc1_w = (const float*)d_in[2];
    const float* fc1_b = (const float*)d_in[3];
    const float* fc_w  = (const float*)d_in[4];
    const float* fc_b  = (const float*)d_in[5];
    const float* A     = (const float*)d_in[6];
    const float* Bm    = (const float*)d_in[7];
    const float* C     = (const float*)d_in[8];
    const float* D     = (const float*)d_in[9];

    // uniform weights -> constant bank (D2D async copies, graph-capturable)
    cudaMemcpyToSymbolAsync(cst, fc1_w,  8 * sizeof(float), CC_FC1W * sizeof(float),
                            cudaMemcpyDeviceToDevice, 0);
    cudaMemcpyToSymbolAsync(cst, fc1_b,  2 * sizeof(float), CC_FC1B * sizeof(float),
                            cudaMemcpyDeviceToDevice, 0);
    cudaMemcpyToSymbolAsync(cst, fc_w,  20 * sizeof(float), CC_FCW  * sizeof(float),
                            cudaMemcpyDeviceToDevice, 0);
    cudaMemcpyToSymbolAsync(cst, fc_b,  10 * sizeof(float), CC_FCB  * sizeof(float),
                            cudaMemcpyDeviceToDevice, 0);
    cudaMemcpyToSymbolAsync(cst, D,      8 * sizeof(float), CC_D    * sizeof(float),
                            cudaMemcpyDeviceToDevice, 0);

    int B = in_sizes[0] / 4;  // x is [B,4]

    float*  out = (float*)d_out;
    float2* oh  = (float2*)out;                   // h: [B,2]
    float4* ost = (float4*)(out + (size_t)2 * B); // new_states: [4,B,2,4,2]

    long long total = (long long)B * 4;           // 4 threads per row
    int grid = (int)((total + THREADS - 1) / THREADS);
    step_ssm_kernel<<<grid, THREADS>>>(
        (const float4*)x, (const float4*)states, A, Bm, C,
        oh, ost, B);
}

// round 8
// speedup vs baseline: 1.0516x; 1.0516x over previous
#include <cuda_runtime.h>

// stepSSM fused kernel, R7: R6 kernel body, single graph node.
//  - NO __constant__ / NO memcpy nodes (R6's 5 memcpyToSymbol nodes cost
//    ~12us graph-replay overhead, swamping the 4us kernel win).
//  - warp-uniform weights read directly via vectorized __ldg (17 broadcast
//    LDGs/thread: fc1 = 2xfloat4+float2, per-layer fc_w float4 + fc_b float2
//    + D scalar, fc10 float4+float2). L1/L2-hit, 1 wavefront each.
//  - q-dependent A/Bm/C in shared as float2 (6 LDS.64 per layer).
//  - 4 threads/row, fully coalesced float4 streaming state I/O.
//
// Inputs (metadata order):
//   0: x[B,4]  1: states[4,B,2,4,2]  2: fc1_w[2,4]  3: fc1_b[2]
//   4: fc_w[5,2,2]  5: fc_b[5,2]  6: A[4,2,4,2]  7: Bm[4,2,4,2]
//   8: C[4,1,2,4,2]  9: D[4,1,2]
// Output: h[B,2] ++ new_states[4,B,2,4,2]  (f32)

#define THREADS 256

__global__ __launch_bounds__(THREADS) void step_ssm_kernel(
    const float4* __restrict__ x,        // [B]
    const float4* __restrict__ states,   // [4*B*4] float4
    const float*  __restrict__ fc1_w,    // 8
    const float*  __restrict__ fc1_b,    // 2
    const float*  __restrict__ fc_w,     // 20
    const float*  __restrict__ fc_b,     // 10
    const float*  __restrict__ A,        // 64
    const float*  __restrict__ Bm,       // 64
    const float*  __restrict__ C,        // 64
    const float*  __restrict__ D,        // 8
    float2*       __restrict__ out_h,      // [B]
    float4*       __restrict__ out_states, // [4*B*4] float4
    int B)
{
    // sABC: [0..31]=A, [32..63]=Bm, [64..95]=C as float2 pairs.
    // pair index for (layer i, quad q, pair j): v = i*8 + q*2 + j.
    __shared__ float2 sABC[96];
    {
        int t = threadIdx.x;
        if (t < 96) {
            const float* src = (t < 32) ? A : (t < 64) ? Bm : C;
            int v = t & 31;
            sABC[t] = make_float2(src[2 * v], src[2 * v + 1]);
        }
    }
    __syncthreads();

    const int t   = blockIdx.x * blockDim.x + threadIdx.x;
    const int row = t >> 2;
    const int q   = t & 3;
    if (row >= B) return;

    const size_t layer_str = (size_t)B * 4;   // float4 units
    const size_t my_off    = (size_t)row * 4 + q;

    // front-load all global reads
    float4 st[4];
#pragma unroll
    for (int i = 0; i < 4; i++)
        st[i] = __ldcs(states + (size_t)i * layer_str + my_off);
    float4 xv = __ldg(x + row);

    // fc1 — vectorized uniform loads (warp-broadcast, L1/L2-hit)
    float4 w0 = __ldg(reinterpret_cast<const float4*>(fc1_w));
    float4 w1 = __ldg(reinterpret_cast<const float4*>(fc1_w) + 1);
    float2 b1 = __ldg(reinterpret_cast<const float2*>(fc1_b));
    float h0 = fmaf(xv.x, w0.x, fmaf(xv.y, w0.y, fmaf(xv.z, w0.z, fmaf(xv.w, w0.w, b1.x))));
    float h1 = fmaf(xv.x, w1.x, fmaf(xv.y, w1.y, fmaf(xv.z, w1.z, fmaf(xv.w, w1.w, b1.y))));

    const int hd = q >> 1;
    const int vq = q * 2;

#pragma unroll
    for (int i = 0; i < 4; i++) {
        const int v = i * 8 + vq;
        float2 a0 = sABC[v],      a1 = sABC[v + 1];
        float2 b0 = sABC[32 + v], b2 = sABC[32 + v + 1];
        float2 c0 = sABC[64 + v], c1 = sABC[64 + v + 1];

        const float u = (hd == 0) ? h0 : h1;

        float nr0 = fmaf(a0.x, st[i].x, fmaf(-a0.y, st[i].y, b0.x * u));
        float ni0 = fmaf(a0.x, st[i].y, fmaf( a0.y, st[i].x, b0.y * u));
        float nr1 = fmaf(a1.x, st[i].z, fmaf(-a1.y, st[i].w, b2.x * u));
        float ni1 = fmaf(a1.x, st[i].w, fmaf( a1.y, st[i].z, b2.y * u));

        __stcs(out_states + (size_t)i * layer_str + my_off,
               make_float4(nr0, ni0, nr1, ni1));

        // partial C-projection (2 f's), reduce within head pair, swap heads
        float acc = fmaf(c0.x, nr0, fmaf(-c0.y, ni0,
                    fmaf(c1.x, nr1, -c1.y * ni1)));
        acc += __shfl_xor_sync(0xFFFFFFFFu, acc, 1);

        float y = fmaf(2.0f, acc, u * __ldg(D + i * 2 + hd));
        y = (y >= 0.0f) ? y : 0.125f * y;
        float yo = __shfl_xor_sync(0xFFFFFFFFu, y, 2);
        float y0 = (hd == 0) ? y  : yo;
        float y1 = (hd == 0) ? yo : y;

        float4 fw = __ldg(reinterpret_cast<const float4*>(fc_w) + i);
        float2 fb = __ldg(reinterpret_cast<const float2*>(fc_b) + i);
        h0 = fmaf(y0, fw.x, fmaf(y1, fw.y, fb.x));
        h1 = fmaf(y0, fw.z, fmaf(y1, fw.w, fb.y));
    }

    // fc10 — lane q==0 writes the contiguous float2
    if (q == 0) {
        float4 fw = __ldg(reinterpret_cast<const float4*>(fc_w) + 4);
        float2 fb = __ldg(reinterpret_cast<const float2*>(fc_b) + 4);
        float o0 = fmaf(h0, fw.x, fmaf(h1, fw.y, fb.x));
        float o1 = fmaf(h0, fw.z, fmaf(h1, fw.w, fb.y));
        out_h[row] = make_float2(o0, o1);
    }
}

extern "C" void kernel_launch(void* const* d_in, const int* in_sizes, int n_in,
                              void* d_out, int out_size)
{
    const float* x     = (const float*)d_in[0];
    const float* states= (const float*)d_in[1];
    const float* fc1_w = (const float*)d_in[2];
    const float* fc1_b = (const float*)d_in[3];
    const float* fc_w  = (const float*)d_in[4];
    const float* fc_b  = (const float*)d_in[5];
    const float* A     = (const float*)d_in[6];
    const float* Bm    = (const float*)d_in[7];
    const float* C     = (const float*)d_in[8];
    const float* D     = (const float*)d_in[9];

    int B = in_sizes[0] / 4;  // x is [B,4]

    float*  out = (float*)d_out;
    float2* oh  = (float2*)out;                   // h: [B,2]
    float4* ost = (float4*)(out + (size_t)2 * B); // new_states: [4,B,2,4,2]

    long long total = (long long)B * 4;           // 4 threads per row
    int grid = (int)((total + THREADS - 1) / THREADS);
    step_ssm_kernel<<<grid, THREADS>>>(
        (const float4*)x, (const float4*)states,
        fc1_w, fc1_b, fc_w, fc_b, A, Bm, C, D,
        oh, ost, B);
}